// round 9
// baseline (speedup 1.0000x reference)
#include <cuda_runtime.h>
#include <math.h>
#include <stdint.h>

#define BN 64
#define CN 512
#define HW 784
#define HW4 196
#define NSEG 8
#define FEPS 1e-12f

#define ROWB 3136                 // bytes per A row (784 floats)
#define GRPB 25088                // 8 rows per TMA group
#define NGRP 8

// dynamic smem layout
#define SM_YW 50176               // 2 stages of GRPB first
#define SM_YS 75264               // yw: 8*784 floats
#define SM_MBAR 78400             // ys: 784 floats
#define SM_TOTAL 78432

// ticket layout: 5x(512 sweep + 64 red), then 512 sweep5, 64 pen, 1 fin
#define BLK576 576
#define T_S5 2880
#define T_PEN 3392
#define T_FIN 3456
#define NITEMS 3457

// ---------------- scratch ----------------
__device__ float g_Yp[2][NSEG * BN * HW];  // Y partials, ping-pong by sweep parity
__device__ float g_ys[2][BN * HW];         // pre-reduced+scaled ys, ping-pong
__device__ float g_u4[BN * CN];            // z4 raw
__device__ float g_nrm[6][BN];             // 0:||x0||^2 1..4:||z_k||^2 5:||w||^2
__device__ float g_lgst[BN], g_inv4[BN], g_pen[BN];
__device__ int   g_cnt[6][BN];
__device__ int   g_rdy[5][BN];
__device__ int   g_pencnt, g_ticket;

__device__ __forceinline__ float ldcg(const float* p) {
    float v; asm volatile("ld.global.cg.f32 %0,[%1];" : "=f"(v) : "l"(p)); return v;
}
__device__ __forceinline__ uint32_t s2u(const void* p) {
    uint32_t a;
    asm("{.reg .u64 t; cvta.to.shared.u64 t, %1; cvt.u32.u64 %0, t;}" : "=r"(a) : "l"(p));
    return a;
}
__device__ __forceinline__ void mbar_wait(uint32_t mb, int par) {
    uint32_t done;
    asm volatile("{\n\t.reg .pred p;\n\t"
        "mbarrier.try_wait.parity.acquire.cta.shared::cta.b64 p, [%1], %2;\n\t"
        "selp.b32 %0,1,0,p;\n\t}" : "=r"(done) : "r"(mb), "r"(par) : "memory");
    if (!done) {
        asm volatile("{\n\t.reg .pred P1;\n\t"
            "W%=:\n\t"
            "mbarrier.try_wait.parity.acquire.cta.shared::cta.b64 P1, [%0], %1, 0x989680;\n\t"
            "@P1 bra.uni D%=;\n\t"
            "bra.uni W%=;\n\t"
            "D%=:\n\t}" :: "r"(mb), "r"(par) : "memory");
    }
}
__device__ __forceinline__ void tma_issue(uint32_t mb, uint32_t dst, const char* src) {
    asm volatile("mbarrier.arrive.expect_tx.shared.b64 _, [%0], %1;"
                 :: "r"(mb), "r"((uint32_t)GRPB) : "memory");
    asm volatile("cp.async.bulk.shared::cta.global.mbarrier::complete_tx::bytes [%0], [%1], %2, [%3];"
                 :: "r"(dst), "l"(src), "r"((uint32_t)GRPB), "r"(mb) : "memory");
}

// ---------------- init: reset state, ||x0||^2 ----------------
__global__ void k_init0(const float* __restrict__ x0) {
    __shared__ float red[16];
    int b = blockIdx.x, t = threadIdx.x;       // 512 threads
    if (t < 6) { g_nrm[t][b] = 0.0f; g_cnt[t][b] = 0; }
    if (t < 5) g_rdy[t][b] = 0;
    if (b == 0 && t == 0) { g_pencnt = 0; g_ticket = 0; }
    float v = x0[b * CN + t];
    float s = v * v;
    #pragma unroll
    for (int o = 16; o; o >>= 1) s += __shfl_xor_sync(0xffffffffu, s, o);
    if ((t & 31) == 0) red[t >> 5] = s;
    __syncthreads();
    if (t < 16) {
        s = red[t];
        #pragma unroll
        for (int o = 8; o; o >>= 1) s += __shfl_xor_sync(0xffffu, s, o);
        if (t == 0) g_nrm[0][b] = s;
    }
}

// ---------------- persistent TMA-fed mega-kernel ----------------
__global__ void __launch_bounds__(256, 2) k_mega(
        const float* __restrict__ A, const float* __restrict__ x0,
        float* __restrict__ out)
{
    extern __shared__ char sm[];
    __shared__ float r1s[8];
    __shared__ int sh_w;
    uint32_t sb = s2u(sm);
    int t = threadIdx.x, warp = t >> 5, lane = t & 31;
    bool k6 = (lane < 4);
    const float4* ys4 = (const float4*)(sm + SM_YS);
    float* ysf = (float*)(sm + SM_YS);
    float* yw = (float*)(sm + SM_YW);

    if (t == 0) {
        asm volatile("mbarrier.init.shared.b64 [%0],1;" :: "r"(sb + SM_MBAR) : "memory");
        asm volatile("mbarrier.init.shared.b64 [%0],1;" :: "r"(sb + SM_MBAR + 8) : "memory");
    }
    __syncthreads();
    asm volatile("fence.proxy.async.shared::cta;" ::: "memory");

    for (;;) {
        if (t == 0) sh_w = atomicAdd(&g_ticket, 1);
        __syncthreads();
        int w = sh_w;
        if (w >= NITEMS) break;

        int kind, sweep = 0, b = 0, seg = 0;
        if (w < 5 * BLK576) {
            int k = w / BLK576, r = w - k * BLK576;
            if (r < 512) { kind = 0; sweep = k; b = r >> 3; seg = r & 7; }
            else         { kind = 1; sweep = k; b = r - 512; }
        } else if (w < T_PEN) { kind = 0; sweep = 5; int r = w - T_S5; b = r >> 3; seg = r & 7; }
        else if (w < T_FIN)   { kind = 2; b = w - T_PEN; }
        else                  { kind = 3; }

        if (kind == 0) {
            // ============ A-sweep item (64 rows, TMA-fed) ============
            if (sweep > 0) {
                if (t == 0) {
                    volatile int* c = &g_rdy[sweep - 1][b];
                    while (!*c) __nanosleep(64);
                    __threadfence();
                }
                __syncthreads();
            }
            float largest = 0.f, inv4 = 1.f;
            if (sweep >= 1) {
                const float* src = g_ys[(sweep - 1) & 1] + b * HW;
                for (int i = t; i < HW; i += 256) ysf[i] = ldcg(src + i);
                if (sweep == 5) { largest = ldcg(&g_lgst[b]); inv4 = ldcg(&g_inv4[b]); }
            }
            __syncthreads();

            const char* Ab = (const char*)A + (size_t)(b * CN + seg * 64) * ROWB;
            if (t == 0) {
                tma_issue(sb + SM_MBAR,     sb,        Ab);
                tma_issue(sb + SM_MBAR + 8, sb + GRPB, Ab + GRPB);
            }

            float4 acc[7];
            #pragma unroll
            for (int k = 0; k < 7; k++) acc[k] = make_float4(0.f, 0.f, 0.f, 0.f);
            float la1 = 0.f;

            #pragma unroll 1
            for (int g = 0; g < NGRP; g++) {
                int st = g & 1, par = (g >> 1) & 1;
                uint32_t mb = sb + SM_MBAR + st * 8;
                mbar_wait(mb, par);

                const float4* Ar = (const float4*)(sm + st * GRPB + warp * ROWB);
                float4 a[7];
                #pragma unroll
                for (int k = 0; k < 6; k++) a[k] = Ar[k * 32 + lane];
                a[6] = k6 ? Ar[192 + lane] : make_float4(0.f, 0.f, 0.f, 0.f);

                int c = seg * 64 + g * 8 + warp;
                float z;
                if (sweep == 0) {
                    z = __ldg(&x0[b * CN + c]);
                } else {
                    float d0 = 0.f, d1 = 0.f, d2 = 0.f, d3 = 0.f;
                    #pragma unroll
                    for (int k = 0; k < 6; k++) {
                        float4 y = ys4[k * 32 + lane];
                        d0 += a[k].x * y.x; d1 += a[k].y * y.y;
                        d2 += a[k].z * y.z; d3 += a[k].w * y.w;
                    }
                    if (k6) {
                        float4 y = ys4[192 + lane];
                        d0 += a[6].x * y.x; d1 += a[6].y * y.y;
                        d2 += a[6].z * y.z; d3 += a[6].w * y.w;
                    }
                    z = (d0 + d1) + (d2 + d3);
                    #pragma unroll
                    for (int o = 16; o; o >>= 1) z += __shfl_xor_sync(0xffffffffu, z, o);
                }
                #pragma unroll
                for (int k = 0; k < 7; k++) {
                    acc[k].x += z * a[k].x; acc[k].y += z * a[k].y;
                    acc[k].z += z * a[k].z; acc[k].w += z * a[k].w;
                }
                if (lane == 0) {
                    if (sweep >= 1 && sweep <= 4) {
                        if (sweep == 4) g_u4[b * CN + c] = z;
                        la1 += z * z;
                    } else if (sweep == 5) {
                        float wv = z - largest * (ldcg(&g_u4[b * CN + c]) * inv4);
                        la1 += wv * wv;
                    }
                }
                __syncthreads();   // all warps done with stage before refill
                if (t == 0 && g < 6)
                    tma_issue(mb, sb + st * GRPB, Ab + (size_t)(g + 2) * GRPB);
            }

            // epilogue: block-reduce acc -> Y partial
            {
                float4* yo = (float4*)(yw + warp * HW);
                #pragma unroll
                for (int k = 0; k < 6; k++) yo[k * 32 + lane] = acc[k];
                if (k6) yo[192 + lane] = acc[6];
                if (lane == 0) r1s[warp] = la1;
            }
            __syncthreads();
            {
                float* Yp = g_Yp[sweep & 1] + (seg * BN + b) * HW;
                for (int i = t; i < HW; i += 256) {
                    float s = 0.f;
                    #pragma unroll
                    for (int ww = 0; ww < 8; ww++) s += yw[ww * HW + i];
                    Yp[i] = s;
                }
            }
            __syncthreads();
            if (t == 0) {
                float s1 = 0.f;
                #pragma unroll
                for (int ww = 0; ww < 8; ww++) s1 += r1s[ww];
                if (sweep >= 1) atomicAdd(&g_nrm[sweep][b], s1);
                __threadfence();
                atomicAdd(&g_cnt[sweep][b], 1);
            }
        } else if (kind == 1) {
            // ============ reduce item: ysum -> scaled ys ============
            if (t == 0) {
                volatile int* c = &g_cnt[sweep][b];
                while (*c < NSEG) __nanosleep(64);
                __threadfence();
            }
            __syncthreads();
            const float* Yp = g_Yp[sweep & 1];
            float scale = 1.0f / fmaxf(sqrtf(ldcg(&g_nrm[sweep][b])), FEPS);
            float* dst = g_ys[sweep & 1] + b * HW;
            if (sweep < 4) {
                for (int i = t; i < HW; i += 256) {
                    float s = 0.f;
                    #pragma unroll
                    for (int sg = 0; sg < NSEG; sg++) s += ldcg(&Yp[(sg * BN + b) * HW + i]);
                    dst[i] = s * scale;
                }
            } else {
                float loc = 0.f;
                for (int i = t; i < HW; i += 256) {
                    float s = 0.f;
                    #pragma unroll
                    for (int sg = 0; sg < NSEG; sg++) s += ldcg(&Yp[(sg * BN + b) * HW + i]);
                    dst[i] = s * scale; loc += s * s;
                }
                #pragma unroll
                for (int o = 16; o; o >>= 1) loc += __shfl_xor_sync(0xffffffffu, loc, o);
                if (lane == 0) r1s[warp] = loc;
                __syncthreads();
                if (t == 0) {
                    float tot = 0.f;
                    #pragma unroll
                    for (int ww = 0; ww < 8; ww++) tot += r1s[ww];
                    g_lgst[b] = tot * scale * scale;   // largest = ||W^T x1||^2
                    g_inv4[b] = scale;
                }
            }
            __syncthreads();
            if (t == 0) { __threadfence(); atomicExch(&g_rdy[sweep][b], 1); }
        } else if (kind == 2) {
            // ============ penalty item (per batch) ============
            if (t == 0) {
                volatile int* c = &g_cnt[5][b];
                while (*c < NSEG) __nanosleep(64);
                __threadfence();
            }
            __syncthreads();
            float largest = ldcg(&g_lgst[b]);
            const float* ysrc = g_ys[0] + b * HW;       // = ysum4 * inv4 (red4)
            float loc = 0.f;
            for (int i = t; i < HW; i += 256) {
                float s5 = 0.f;
                #pragma unroll
                for (int sg = 0; sg < NSEG; sg++) s5 += ldcg(&g_Yp[1][(sg * BN + b) * HW + i]);
                float y6 = s5 - largest * ldcg(&ysrc[i]);   // W^T w
                loc += y6 * y6;
            }
            #pragma unroll
            for (int o = 16; o; o >>= 1) loc += __shfl_xor_sync(0xffffffffu, loc, o);
            if (lane == 0) r1s[warp] = loc;
            __syncthreads();
            if (t == 0) {
                float num6 = 0.f;
                #pragma unroll
                for (int ww = 0; ww < 8; ww++) num6 += r1s[ww];
                float smallest = num6 / ldcg(&g_nrm[5][b]);  // ||W^T w||^2/||w||^2
                float rr = largest / smallest - 1.0f;
                g_pen[b] = rr * rr;
                __threadfence();
                atomicAdd(&g_pencnt, 1);
            }
        } else {
            // ============ final sum ============
            if (t == 0) {
                volatile int* c = &g_pencnt;
                while (*c < BN) __nanosleep(64);
                __threadfence();
            }
            __syncthreads();
            float p = (t < BN) ? ldcg(&g_pen[t]) : 0.f;
            #pragma unroll
            for (int o = 16; o; o >>= 1) p += __shfl_xor_sync(0xffffffffu, p, o);
            if (lane == 0) r1s[warp] = p;
            __syncthreads();
            if (t == 0) out[0] = (r1s[0] + r1s[1]) / (float)BN;
        }
        __syncthreads();
    }
}

// ---------------- launch ----------------
extern "C" void kernel_launch(void* const* d_in, const int* in_sizes, int n_in,
                              void* d_out, int out_size) {
    const float* A  = (const float*)d_in[0];
    const float* x0 = (const float*)d_in[1];
    if (n_in >= 2 && in_sizes[0] < in_sizes[1]) {   // safety: A is the big one
        const float* t = A; A = x0; x0 = t;
    }
    float* out = (float*)d_out;
    (void)out_size;

    cudaFuncSetAttribute(k_mega, cudaFuncAttributeMaxDynamicSharedMemorySize, SM_TOTAL);

    int nsm = 148;
    cudaDeviceGetAttribute(&nsm, cudaDevAttrMultiProcessorCount, 0);
    int grid = nsm * 2;

    k_init0<<<BN, 512>>>(x0);
    k_mega<<<grid, 256, SM_TOTAL>>>(A, x0, out);
}

// round 10
// speedup vs baseline: 1.1503x; 1.1503x over previous
#include <cuda_runtime.h>
#include <math.h>

#define BN 64
#define CN 512
#define HW 784
#define HW4 196
#define R_TOT (BN * CN)
#define FEPS 1e-12f

// ---------------- scratch (static __device__, no allocation) ----------------
__device__ float g_Y[6][BN * HW];         // summed W^T z per sweep (atomic-accumulated)
__device__ float g_u4[BN * CN];           // z4 raw
__device__ float g_nrm[6][BN];            // 0:||x0||^2 1..4:||z_k||^2 5:||w||^2
__device__ float g_lgst[BN], g_inv4[BN], g_pen[BN];

// L2 evict_last policy for A loads (103MB vs 126MB L2)
__device__ __forceinline__ unsigned long long mk_policy() {
    unsigned long long pol;
    asm("createpolicy.fractional.L2::evict_last.b64 %0, 1.0;" : "=l"(pol));
    return pol;
}
__device__ __forceinline__ float4 ldg_el(const float4* p, unsigned long long pol) {
    float4 r;
    asm volatile("ld.global.nc.L2::cache_hint.v4.f32 {%0,%1,%2,%3}, [%4], %5;"
                 : "=f"(r.x), "=f"(r.y), "=f"(r.z), "=f"(r.w) : "l"(p), "l"(pol));
    return r;
}

// ---------------- init: zero Y+accums, ||x0||^2 ----------------
__global__ void k_init0(const float* __restrict__ x0) {
    __shared__ float red[16];
    int b = blockIdx.x, t = threadIdx.x;       // 64 blocks x 512 threads
    for (int s = 0; s < 6; s++)
        for (int i = t; i < HW; i += 512) g_Y[s][b * HW + i] = 0.f;
    if (t < 6) g_nrm[t][b] = 0.0f;
    float v = x0[b * CN + t];
    float s = v * v;
    #pragma unroll
    for (int o = 16; o; o >>= 1) s += __shfl_xor_sync(0xffffffffu, s, o);
    if ((t & 31) == 0) red[t >> 5] = s;
    __syncthreads();
    if (t < 16) {
        s = red[t];
        #pragma unroll
        for (int o = 8; o; o >>= 1) s += __shfl_xor_sync(0xffffu, s, o);
        if (t == 0) g_nrm[0][b] = s;
    }
}

// ---------------- sweep kernel (templated, balanced static partition) -------
// SWEEP 0: z = x0[c]               (axpy only)
// SWEEP 1..4: z = A row . ys, ys = Y[S-1]*rsqrt(nrm[S-1]); ||z||^2 -> nrm[S];
//             SWEEP 4 also stores z -> g_u4
// SWEEP 5: ys = Y[4]*inv4; w = z - largest*(u4*inv4); ||w||^2 -> nrm[5]
template<int SWEEP>
__global__ void __launch_bounds__(256, 2) k_ap(
        const float4* __restrict__ A4, const float* __restrict__ x0, int G)
{
    __shared__ float ys[HW];
    __shared__ float yw[8][HW];
    __shared__ float r1s[8];
    int t = threadIdx.x, warp = t >> 5, lane = t & 31;   // 256 threads
    bool k6 = (lane < 4);
    unsigned long long pol = mk_policy();
    const float4* ys4 = (const float4*)ys;

    int rs = (int)((long long)blockIdx.x * R_TOT / G);
    int re = (int)((long long)(blockIdx.x + 1) * R_TOT / G);

    bool first = true;
    while (rs < re) {
        int b = rs >> 9;
        int cs = rs & (CN - 1);
        int ce = re - (b << 9); if (ce > CN) ce = CN;

        if (!first) __syncthreads();   // protect ys/yw reuse across subranges
        first = false;

        float largest = 0.f, inv4 = 1.f;
        if (SWEEP >= 1 && SWEEP <= 4) {
            float sc = 1.0f / fmaxf(sqrtf(g_nrm[SWEEP - 1][b]), FEPS);
            for (int i = t; i < HW; i += 256) ys[i] = g_Y[SWEEP - 1][b * HW + i] * sc;
        } else if (SWEEP == 5) {
            largest = g_lgst[b]; inv4 = g_inv4[b];
            for (int i = t; i < HW; i += 256) ys[i] = g_Y[4][b * HW + i] * inv4;
        }
        __syncthreads();

        float4 acc[7];
        #pragma unroll
        for (int k = 0; k < 7; k++) acc[k] = make_float4(0.f, 0.f, 0.f, 0.f);
        float la1 = 0.f;

        // row-per-warp, stride 8, register double-buffered A pipeline
        int c = cs + warp;
        float4 cur[7], nxt[7];
        if (c < ce) {
            const float4* Ar = A4 + (size_t)(b * CN + c) * HW4;
            #pragma unroll
            for (int k = 0; k < 6; k++) cur[k] = ldg_el(Ar + k * 32 + lane, pol);
            cur[6] = k6 ? ldg_el(Ar + 192 + lane, pol) : make_float4(0.f, 0.f, 0.f, 0.f);
        }
        for (; c < ce; c += 8) {
            if (c + 8 < ce) {
                const float4* Arn = A4 + (size_t)(b * CN + c + 8) * HW4;
                #pragma unroll
                for (int k = 0; k < 6; k++) nxt[k] = ldg_el(Arn + k * 32 + lane, pol);
                nxt[6] = k6 ? ldg_el(Arn + 192 + lane, pol) : make_float4(0.f, 0.f, 0.f, 0.f);
            }
            float z;
            if (SWEEP == 0) {
                z = __ldg(&x0[b * CN + c]);
            } else {
                float d0 = 0.f, d1 = 0.f, d2 = 0.f, d3 = 0.f;
                #pragma unroll
                for (int k = 0; k < 6; k++) {
                    float4 y = ys4[k * 32 + lane];
                    d0 += cur[k].x * y.x; d1 += cur[k].y * y.y;
                    d2 += cur[k].z * y.z; d3 += cur[k].w * y.w;
                }
                if (k6) {
                    float4 y = ys4[192 + lane];
                    d0 += cur[6].x * y.x; d1 += cur[6].y * y.y;
                    d2 += cur[6].z * y.z; d3 += cur[6].w * y.w;
                }
                z = (d0 + d1) + (d2 + d3);
                #pragma unroll
                for (int o = 16; o; o >>= 1) z += __shfl_xor_sync(0xffffffffu, z, o);
            }
            #pragma unroll
            for (int k = 0; k < 7; k++) {
                acc[k].x += z * cur[k].x; acc[k].y += z * cur[k].y;
                acc[k].z += z * cur[k].z; acc[k].w += z * cur[k].w;
            }
            if (lane == 0) {
                if (SWEEP >= 1 && SWEEP <= 4) {
                    if (SWEEP == 4) g_u4[b * CN + c] = z;
                    la1 += z * z;
                } else if (SWEEP == 5) {
                    float wv = z - largest * (g_u4[b * CN + c] * inv4);
                    la1 += wv * wv;
                }
            }
            if (c + 8 < ce) {
                #pragma unroll
                for (int k = 0; k < 7; k++) cur[k] = nxt[k];
            }
        }

        // block-reduce warp accs -> atomicAdd into g_Y[SWEEP][b]
        {
            float4* yo = (float4*)yw[warp];
            #pragma unroll
            for (int k = 0; k < 6; k++) yo[k * 32 + lane] = acc[k];
            if (k6) yo[192 + lane] = acc[6];
            if (lane == 0) r1s[warp] = la1;
        }
        __syncthreads();
        {
            float* Yp = &g_Y[SWEEP][b * HW];
            for (int i = t; i < HW; i += 256) {
                float s = 0.f;
                #pragma unroll
                for (int w = 0; w < 8; w++) s += yw[w][i];
                atomicAdd(&Yp[i], s);
            }
        }
        if (t == 0 && SWEEP >= 1) {
            float s1 = 0.f;
            #pragma unroll
            for (int w = 0; w < 8; w++) s1 += r1s[w];
            atomicAdd(&g_nrm[SWEEP][b], s1);
        }
        rs = (b << 9) + ce;
    }
}

// ---------------- mid: largest = ||Y4||^2/||z4||^2, inv4 ----------------
__global__ void k_mid() {
    __shared__ float red[8];
    int b = blockIdx.x, t = threadIdx.x, warp = t >> 5, lane = t & 31;  // 256 thr
    float loc = 0.f;
    for (int i = t; i < HW; i += 256) {
        float s = g_Y[4][b * HW + i];
        loc += s * s;
    }
    #pragma unroll
    for (int o = 16; o; o >>= 1) loc += __shfl_xor_sync(0xffffffffu, loc, o);
    if (lane == 0) red[warp] = loc;
    __syncthreads();
    if (t == 0) {
        float tot = 0.f;
        #pragma unroll
        for (int w = 0; w < 8; w++) tot += red[w];
        float inv4 = 1.0f / fmaxf(sqrtf(g_nrm[4][b]), FEPS);
        g_inv4[b] = inv4;
        g_lgst[b] = tot * inv4 * inv4;     // largest = ||W^T x1||^2
    }
}

// ---------------- pen: y6 = Y5 - largest*inv4*Y4; per-batch penalty ---------
__global__ void k_pen() {
    __shared__ float red[8];
    int b = blockIdx.x, t = threadIdx.x, warp = t >> 5, lane = t & 31;  // 256 thr
    float largest = g_lgst[b], f = largest * g_inv4[b];
    float loc = 0.f;
    for (int i = t; i < HW; i += 256) {
        float y6 = g_Y[5][b * HW + i] - f * g_Y[4][b * HW + i];   // W^T w
        loc += y6 * y6;
    }
    #pragma unroll
    for (int o = 16; o; o >>= 1) loc += __shfl_xor_sync(0xffffffffu, loc, o);
    if (lane == 0) red[warp] = loc;
    __syncthreads();
    if (t == 0) {
        float num6 = 0.f;
        #pragma unroll
        for (int w = 0; w < 8; w++) num6 += red[w];
        float smallest = num6 / g_nrm[5][b];     // ||W^T w||^2 / ||w||^2
        float r = largest / smallest - 1.0f;
        g_pen[b] = r * r;
    }
}

// ---------------- final: sum penalties / B ----------------
__global__ void k_sum(float* __restrict__ out) {
    __shared__ float red[2];
    int t = threadIdx.x;                        // 64 threads
    float p = g_pen[t];
    #pragma unroll
    for (int o = 16; o; o >>= 1) p += __shfl_xor_sync(0xffffffffu, p, o);
    if ((t & 31) == 0) red[t >> 5] = p;
    __syncthreads();
    if (t == 0) out[0] = (red[0] + red[1]) / (float)BN;
}

// ---------------- launch ----------------
extern "C" void kernel_launch(void* const* d_in, const int* in_sizes, int n_in,
                              void* d_out, int out_size) {
    const float* A  = (const float*)d_in[0];
    const float* x0 = (const float*)d_in[1];
    if (n_in >= 2 && in_sizes[0] < in_sizes[1]) {   // safety: A is the big one
        const float* t = A; A = x0; x0 = t;
    }
    const float4* A4 = (const float4*)A;
    float* out = (float*)d_out;
    (void)out_size;

    int nsm = 148;
    cudaDeviceGetAttribute(&nsm, cudaDevAttrMultiProcessorCount, 0);
    int G = nsm * 2;                         // exactly-resident balanced grid

    k_init0<<<BN, 512>>>(x0);

    k_ap<0><<<G, 256>>>(A4, x0, G);          // Y0 = W^T x0
    k_ap<1><<<G, 256>>>(A4, x0, G);          // z1, Y1
    k_ap<2><<<G, 256>>>(A4, x0, G);          // z2, Y2
    k_ap<3><<<G, 256>>>(A4, x0, G);          // z3, Y3
    k_ap<4><<<G, 256>>>(A4, x0, G);          // z4 -> u4, Y4

    k_mid<<<BN, 256>>>();                    // largest, inv4

    k_ap<5><<<G, 256>>>(A4, x0, G);          // ||w||^2, Y5

    k_pen<<<BN, 256>>>();                    // per-batch penalty
    k_sum<<<1, 64>>>(out);
}

// round 13
// speedup vs baseline: 1.5446x; 1.3428x over previous
#include <cuda_runtime.h>
#include <math.h>
#include <stdint.h>

#define BN 64
#define CN 512
#define HW 784
#define HW4 196
#define R_TOT (BN * CN)
#define FEPS 1e-12f

#define ROWB 3136                  // bytes per A row
#define DEPTH 3                    // cp.async stages per warp
#define SM_PIPE (8 * DEPTH * ROWB) // 75264
#define SM_YW   (SM_PIPE)          // yw: 8*784 floats at this offset
#define SM_R1S  (SM_PIPE + 8 * HW * 4)
#define SM_TOTAL (SM_R1S + 32)

// ---------------- scratch (static __device__, no allocation) ----------------
__device__ __align__(16) float g_Y[6][BN * HW];  // summed W^T z per sweep
__device__ float g_u4[BN * CN];
__device__ float g_nrm[6][BN];            // 0:||x0||^2 1..4:||z_k||^2 5:||w||^2
__device__ float g_lgst[BN], g_inv4[BN], g_pen[BN];

__device__ __forceinline__ uint32_t s2u(const void* p) {
    uint32_t a;
    asm("{.reg .u64 t; cvta.to.shared.u64 t, %1; cvt.u32.u64 %0, t;}" : "=r"(a) : "l"(p));
    return a;
}
// Plain cp.async (LDGSTS), no cache-hint: the hinted form traps on sm_103a.
__device__ __forceinline__ void cpa16(uint32_t dst, const float4* src) {
    asm volatile("cp.async.cg.shared.global [%0], [%1], 16;"
                 :: "r"(dst), "l"(src) : "memory");
}
#define CPA_COMMIT() asm volatile("cp.async.commit_group;" ::: "memory")
#define CPA_WAIT2()  asm volatile("cp.async.wait_group 2;" ::: "memory")
#define CPA_WAIT0()  asm volatile("cp.async.wait_group 0;" ::: "memory")

// ---------------- init: zero Y+accums, ||x0||^2 ----------------
__global__ void k_init0(const float* __restrict__ x0) {
    __shared__ float red[16];
    int b = blockIdx.x, t = threadIdx.x;       // 64 blocks x 512 threads
    for (int s = 0; s < 6; s++)
        for (int i = t; i < HW; i += 512) g_Y[s][b * HW + i] = 0.f;
    if (t < 6) g_nrm[t][b] = 0.0f;
    float v = x0[b * CN + t];
    float s = v * v;
    #pragma unroll
    for (int o = 16; o; o >>= 1) s += __shfl_xor_sync(0xffffffffu, s, o);
    if ((t & 31) == 0) red[t >> 5] = s;
    __syncthreads();
    if (t < 16) {
        s = red[t];
        #pragma unroll
        for (int o = 8; o; o >>= 1) s += __shfl_xor_sync(0xffffu, s, o);
        if (t == 0) g_nrm[0][b] = s;
    }
}

// ---------------- sweep kernel: cp.async-fed, balanced static partition -----
// SWEEP 0: z = x0[c] (axpy only)
// SWEEP 1..4: z = A_row . ys (ys = Y[S-1]*rsqrt(nrm[S-1])); ||z||^2 -> nrm[S];
//             SWEEP 4 stores z -> g_u4
// SWEEP 5: ys = Y[4]*inv4; w = z - largest*(u4*inv4); ||w||^2 -> nrm[5]
template<int SWEEP>
__global__ void __launch_bounds__(256, 2) k_ap(
        const float4* __restrict__ A4, const float* __restrict__ x0, int G)
{
    extern __shared__ char sm[];
    float* yw = (float*)(sm + SM_YW);
    float* r1s = (float*)(sm + SM_R1S);
    int t = threadIdx.x, warp = t >> 5, lane = t & 31;   // 256 threads
    bool k6 = (lane < 4);
    uint32_t pbase = s2u(sm) + warp * (DEPTH * ROWB) + lane * 16;
    const float4* pipe4 = (const float4*)(sm + warp * (DEPTH * ROWB));

    int rs = (int)((long long)blockIdx.x * R_TOT / G);
    int re = (int)((long long)(blockIdx.x + 1) * R_TOT / G);

    bool first = true;
    while (rs < re) {
        int b = rs >> 9;
        int cs = rs & (CN - 1);
        int ce = re - (b << 9); if (ce > CN) ce = CN;

        if (!first) __syncthreads();   // protect yw reuse across subranges
        first = false;

        // ---- ys in registers (28 floats/thread) ----
        float4 ysr[7];
        float largest = 0.f, inv4 = 1.f;
        if (SWEEP >= 1) {
            float sc;
            const float4* Ysrc;
            if (SWEEP <= 4) {
                sc = 1.0f / fmaxf(sqrtf(g_nrm[SWEEP - 1][b]), FEPS);
                Ysrc = (const float4*)(&g_Y[SWEEP - 1][b * HW]);
            } else {
                largest = g_lgst[b]; inv4 = g_inv4[b];
                sc = inv4;
                Ysrc = (const float4*)(&g_Y[4][b * HW]);
            }
            #pragma unroll
            for (int k = 0; k < 6; k++) {
                float4 y = __ldg(Ysrc + k * 32 + lane);
                ysr[k] = make_float4(y.x * sc, y.y * sc, y.z * sc, y.w * sc);
            }
            if (k6) {
                float4 y = __ldg(Ysrc + 192 + lane);
                ysr[6] = make_float4(y.x * sc, y.y * sc, y.z * sc, y.w * sc);
            } else ysr[6] = make_float4(0.f, 0.f, 0.f, 0.f);
        }

        float4 acc[7];
        #pragma unroll
        for (int k = 0; k < 7; k++) acc[k] = make_float4(0.f, 0.f, 0.f, 0.f);
        float la1 = 0.f;

        // ---- per-warp cp.async pipeline over rows c = cs+warp, step 8 ----
        int c0 = cs + warp;
        // prologue: issue DEPTH rows (guarded), one commit per stage
        #pragma unroll
        for (int d = 0; d < DEPTH; d++) {
            int c = c0 + d * 8;
            if (c < ce) {
                const float4* src = A4 + (size_t)(b * CN + c) * HW4;
                uint32_t dst = pbase + d * ROWB;
                #pragma unroll
                for (int k = 0; k < 6; k++) cpa16(dst + k * 512, src + k * 32 + lane);
                if (k6) cpa16(dst + 6 * 512, src + 192 + lane);
            }
            CPA_COMMIT();
        }

        int stage = 0;
        for (int c = c0; c < ce; c += 8) {
            CPA_WAIT2();   // oldest group (this row) complete
            const float4* Ar = pipe4 + stage * (ROWB / 16);
            float4 a[7];
            #pragma unroll
            for (int k = 0; k < 6; k++) a[k] = Ar[k * 32 + lane];
            a[6] = k6 ? Ar[192 + lane] : make_float4(0.f, 0.f, 0.f, 0.f);

            // refill this stage with row c + DEPTH*8 (guarded), uniform commit
            {
                int cn = c + DEPTH * 8;
                if (cn < ce) {
                    const float4* src = A4 + (size_t)(b * CN + cn) * HW4;
                    uint32_t dst = pbase + stage * ROWB;
                    #pragma unroll
                    for (int k = 0; k < 6; k++) cpa16(dst + k * 512, src + k * 32 + lane);
                    if (k6) cpa16(dst + 6 * 512, src + 192 + lane);
                }
                CPA_COMMIT();
            }

            float z;
            if (SWEEP == 0) {
                z = __ldg(&x0[b * CN + c]);
            } else {
                float d0 = 0.f, d1 = 0.f, d2 = 0.f, d3 = 0.f;
                #pragma unroll
                for (int k = 0; k < 7; k++) {
                    d0 += a[k].x * ysr[k].x; d1 += a[k].y * ysr[k].y;
                    d2 += a[k].z * ysr[k].z; d3 += a[k].w * ysr[k].w;
                }
                z = (d0 + d1) + (d2 + d3);
                #pragma unroll
                for (int o = 16; o; o >>= 1) z += __shfl_xor_sync(0xffffffffu, z, o);
            }
            #pragma unroll
            for (int k = 0; k < 7; k++) {
                acc[k].x += z * a[k].x; acc[k].y += z * a[k].y;
                acc[k].z += z * a[k].z; acc[k].w += z * a[k].w;
            }
            if (lane == 0) {
                if (SWEEP >= 1 && SWEEP <= 4) {
                    if (SWEEP == 4) g_u4[b * CN + c] = z;
                    la1 += z * z;
                } else if (SWEEP == 5) {
                    float wv = z - largest * (g_u4[b * CN + c] * inv4);
                    la1 += wv * wv;
                }
            }
            stage = (stage + 1 == DEPTH) ? 0 : stage + 1;
        }
        CPA_WAIT0();   // drain before stage memory reuse next subrange

        // ---- block-reduce warp accs -> atomicAdd into g_Y[SWEEP][b] ----
        {
            float4* yo = (float4*)(yw + warp * HW);
            #pragma unroll
            for (int k = 0; k < 6; k++) yo[k * 32 + lane] = acc[k];
            if (k6) yo[192 + lane] = acc[6];
            if (lane == 0) r1s[warp] = la1;
        }
        __syncthreads();
        {
            float* Yp = &g_Y[SWEEP][b * HW];
            for (int i = t; i < HW; i += 256) {
                float s = 0.f;
                #pragma unroll
                for (int w = 0; w < 8; w++) s += yw[w * HW + i];
                atomicAdd(&Yp[i], s);
            }
        }
        if (t == 0 && SWEEP >= 1) {
            float s1 = 0.f;
            #pragma unroll
            for (int w = 0; w < 8; w++) s1 += r1s[w];
            atomicAdd(&g_nrm[SWEEP][b], s1);
        }
        rs = (b << 9) + ce;
    }
}

// ---------------- mid: largest = ||Y4||^2/||z4||^2, inv4 ----------------
__global__ void k_mid() {
    __shared__ float red[8];
    int b = blockIdx.x, t = threadIdx.x, warp = t >> 5, lane = t & 31;  // 256 thr
    float loc = 0.f;
    for (int i = t; i < HW; i += 256) {
        float s = g_Y[4][b * HW + i];
        loc += s * s;
    }
    #pragma unroll
    for (int o = 16; o; o >>= 1) loc += __shfl_xor_sync(0xffffffffu, loc, o);
    if (lane == 0) red[warp] = loc;
    __syncthreads();
    if (t == 0) {
        float tot = 0.f;
        #pragma unroll
        for (int w = 0; w < 8; w++) tot += red[w];
        float inv4 = 1.0f / fmaxf(sqrtf(g_nrm[4][b]), FEPS);
        g_inv4[b] = inv4;
        g_lgst[b] = tot * inv4 * inv4;     // largest = ||W^T x1||^2
    }
}

// ---------------- pen: y6 = Y5 - largest*inv4*Y4; per-batch penalty ---------
__global__ void k_pen() {
    __shared__ float red[8];
    int b = blockIdx.x, t = threadIdx.x, warp = t >> 5, lane = t & 31;  // 256 thr
    float largest = g_lgst[b], f = largest * g_inv4[b];
    float loc = 0.f;
    for (int i = t; i < HW; i += 256) {
        float y6 = g_Y[5][b * HW + i] - f * g_Y[4][b * HW + i];   // W^T w
        loc += y6 * y6;
    }
    #pragma unroll
    for (int o = 16; o; o >>= 1) loc += __shfl_xor_sync(0xffffffffu, loc, o);
    if (lane == 0) red[warp] = loc;
    __syncthreads();
    if (t == 0) {
        float num6 = 0.f;
        #pragma unroll
        for (int w = 0; w < 8; w++) num6 += red[w];
        float smallest = num6 / g_nrm[5][b];     // ||W^T w||^2 / ||w||^2
        float r = largest / smallest - 1.0f;
        g_pen[b] = r * r;
    }
}

// ---------------- final: sum penalties / B ----------------
__global__ void k_sum(float* __restrict__ out) {
    __shared__ float red[2];
    int t = threadIdx.x;                        // 64 threads
    float p = g_pen[t];
    #pragma unroll
    for (int o = 16; o; o >>= 1) p += __shfl_xor_sync(0xffffffffu, p, o);
    if ((t & 31) == 0) red[t >> 5] = p;
    __syncthreads();
    if (t == 0) out[0] = (red[0] + red[1]) / (float)BN;
}

// ---------------- launch ----------------
extern "C" void kernel_launch(void* const* d_in, const int* in_sizes, int n_in,
                              void* d_out, int out_size) {
    const float* A  = (const float*)d_in[0];
    const float* x0 = (const float*)d_in[1];
    if (n_in >= 2 && in_sizes[0] < in_sizes[1]) {   // safety: A is the big one
        const float* t = A; A = x0; x0 = t;
    }
    const float4* A4 = (const float4*)A;
    float* out = (float*)d_out;
    (void)out_size;

    cudaFuncSetAttribute(k_ap<0>, cudaFuncAttributeMaxDynamicSharedMemorySize, SM_TOTAL);
    cudaFuncSetAttribute(k_ap<1>, cudaFuncAttributeMaxDynamicSharedMemorySize, SM_TOTAL);
    cudaFuncSetAttribute(k_ap<2>, cudaFuncAttributeMaxDynamicSharedMemorySize, SM_TOTAL);
    cudaFuncSetAttribute(k_ap<3>, cudaFuncAttributeMaxDynamicSharedMemorySize, SM_TOTAL);
    cudaFuncSetAttribute(k_ap<4>, cudaFuncAttributeMaxDynamicSharedMemorySize, SM_TOTAL);
    cudaFuncSetAttribute(k_ap<5>, cudaFuncAttributeMaxDynamicSharedMemorySize, SM_TOTAL);

    int nsm = 148;
    cudaDeviceGetAttribute(&nsm, cudaDevAttrMultiProcessorCount, 0);
    int G = nsm * 2;                         // exactly-resident balanced grid

    k_init0<<<BN, 512>>>(x0);

    k_ap<0><<<G, 256, SM_TOTAL>>>(A4, x0, G);   // Y0 = W^T x0
    k_ap<1><<<G, 256, SM_TOTAL>>>(A4, x0, G);   // z1, Y1
    k_ap<2><<<G, 256, SM_TOTAL>>>(A4, x0, G);   // z2, Y2
    k_ap<3><<<G, 256, SM_TOTAL>>>(A4, x0, G);   // z3, Y3
    k_ap<4><<<G, 256, SM_TOTAL>>>(A4, x0, G);   // z4 -> u4, Y4

    k_mid<<<BN, 256>>>();                       // largest, inv4

    k_ap<5><<<G, 256, SM_TOTAL>>>(A4, x0, G);   // ||w||^2, Y5

    k_pen<<<BN, 256>>>();                       // per-batch penalty
    k_sum<<<1, 64>>>(out);
}